// round 5
// baseline (speedup 1.0000x reference)
#include <cuda_runtime.h>
#include <math.h>
#include <stdint.h>

#define S_LEN 2048
#define DMODEL 768
#define NHEAD 12
#define HDIM 64
#define FFN 3072
#define NLAYER 2

typedef unsigned long long u64;

// ---------------- scratch ----------------
__device__ float g_x  [S_LEN * DMODEL];
__device__ float g_h  [S_LEN * DMODEL];
__device__ float g_qkv[S_LEN * 3 * DMODEL];
__device__ float g_att[S_LEN * DMODEL];
__device__ float g_ffn[S_LEN * FFN];

// ---------------- f32x2 packed math ----------------
__device__ __forceinline__ u64 pack2(float x, float y) {
    u64 d;
    asm("mov.b64 %0, {%1, %2};" : "=l"(d) : "f"(x), "f"(y));
    return d;
}
__device__ __forceinline__ u64 dup2(float x) {
    u64 d;
    asm("mov.b64 %0, {%1, %1};" : "=l"(d) : "f"(x));
    return d;
}
__device__ __forceinline__ void unpack2(u64 v, float& lo, float& hi) {
    asm("mov.b64 {%0, %1}, %2;" : "=f"(lo), "=f"(hi) : "l"(v));
}
// c += a * b (elementwise packed fp32 pair)
__device__ __forceinline__ void ffma2(u64& c, u64 a, u64 b) {
    asm("fma.rn.f32x2 %0, %1, %2, %0;" : "+l"(c) : "l"(a), "l"(b));
}
// c = c * a + b
__device__ __forceinline__ void ffma2_scale(u64& c, u64 a, u64 b) {
    asm("fma.rn.f32x2 %0, %0, %1, %2;" : "+l"(c) : "l"(a), "l"(b));
}

// ---------------- embed ----------------
__global__ __launch_bounds__(256)
void embed_kernel(const int* __restrict__ idx, const float* __restrict__ emb,
                  const float* __restrict__ pe, float* __restrict__ x)
{
    int t = blockIdx.x;
    int tok = idx[t];
    const float* ep = emb + (size_t)tok * DMODEL;
    const float* pp = pe + (size_t)t * DMODEL;
    float* xp = x + (size_t)t * DMODEL;
    for (int d = threadIdx.x; d < DMODEL; d += 256)
        xp[d] = ep[d] + pp[d];
}

// ---------------- layernorm (fp32 in/out) ----------------
__device__ __forceinline__ float block_reduce_sum(float v, float* red)
{
    #pragma unroll
    for (int o = 16; o > 0; o >>= 1) v += __shfl_xor_sync(0xffffffffu, v, o);
    __syncthreads();
    if ((threadIdx.x & 31) == 0) red[threadIdx.x >> 5] = v;
    __syncthreads();
    float t = 0.f;
    #pragma unroll
    for (int i = 0; i < 8; i++) t += red[i];
    return t;
}

__global__ __launch_bounds__(256)
void ln_kernel(const float* __restrict__ x, const float* __restrict__ s,
               const float* __restrict__ b, float* __restrict__ o)
{
    __shared__ float red[8];
    int row = blockIdx.x;
    int tid = threadIdx.x;
    const float* xp = x + (size_t)row * DMODEL;
    float v0 = xp[tid], v1 = xp[tid + 256], v2 = xp[tid + 512];
    float mean = block_reduce_sum(v0 + v1 + v2, red) * (1.0f / DMODEL);
    float d0 = v0 - mean, d1 = v1 - mean, d2 = v2 - mean;
    float var = block_reduce_sum(d0 * d0 + d1 * d1 + d2 * d2, red) * (1.0f / DMODEL);
    float r = rsqrtf(var + 1e-5f);
    float* op = o + (size_t)row * DMODEL;
    op[tid]       = d0 * r * s[tid]       + b[tid];
    op[tid + 256] = d1 * r * s[tid + 256] + b[tid + 256];
    op[tid + 512] = d2 * r * s[tid + 512] + b[tid + 512];
}

// ---------------- packed-fp32 GEMM: C[M,N] = A[M,K] @ B[K,N] ----------------
// Tile: MT x 128, MT = R*16 (R = rows per thread, 4 or 8). KSLAB=16.
// Thread grid 16x16, microtile R x 8 (4 packed column-pairs).
// MODE 0: +bias   MODE 1: gelu(+bias)   MODE 2: +bias+resid
template<int R, int MODE>
__global__ __launch_bounds__(256)
void pgemm_kernel(const float* __restrict__ A, const float* __restrict__ B,
                  const float* __restrict__ bias, const float* __restrict__ resid,
                  float* __restrict__ C, int M, int N, int K)
{
    constexpr int MT = R * 16;
    __shared__ float As[16][MT];
    __shared__ float Bs[16][128];

    int tid = threadIdx.x;
    int m0 = blockIdx.y * MT, n0 = blockIdx.x * 128;
    int tr = (tid >> 4) * R, tc = (tid & 15) * 8;

    // A loader: thread handles row am, k-quad(s) starting at ak
    int am = tid & (MT - 1);
    int ak = (R == 8) ? ((tid >> 7) * 8) : ((tid >> 6) * 4);
    const float* Ap = A + (size_t)(m0 + am) * K + ak;
    // B loader: row bk, cols bc..bc+7
    int bk = tid >> 4, bc = (tid & 15) * 8;
    const float* Bp = B + (size_t)bk * N + n0 + bc;

    float4 pa[R / 4], pb[2];
    #pragma unroll
    for (int q = 0; q < R / 4; q++) pa[q] = *(const float4*)(Ap + q * 4);
    pb[0] = *(const float4*)(Bp);
    pb[1] = *(const float4*)(Bp + 4);

    u64 acc2[R][4];
    #pragma unroll
    for (int i = 0; i < R; i++)
        #pragma unroll
        for (int j = 0; j < 4; j++) acc2[i][j] = 0ull;

    for (int k0 = 0; k0 < K; k0 += 16) {
        __syncthreads();
        #pragma unroll
        for (int q = 0; q < R / 4; q++) {
            As[ak + q * 4 + 0][am] = pa[q].x;
            As[ak + q * 4 + 1][am] = pa[q].y;
            As[ak + q * 4 + 2][am] = pa[q].z;
            As[ak + q * 4 + 3][am] = pa[q].w;
        }
        *(float4*)&Bs[bk][bc]     = pb[0];
        *(float4*)&Bs[bk][bc + 4] = pb[1];
        __syncthreads();

        int kn = k0 + 16;
        if (kn < K) {
            #pragma unroll
            for (int q = 0; q < R / 4; q++) pa[q] = *(const float4*)(Ap + kn + q * 4);
            pb[0] = *(const float4*)(Bp + (size_t)kn * N);
            pb[1] = *(const float4*)(Bp + (size_t)kn * N + 4);
        }

        #pragma unroll
        for (int k = 0; k < 16; k++) {
            ulonglong2 b01 = *(const ulonglong2*)&Bs[k][tc];
            ulonglong2 b23 = *(const ulonglong2*)&Bs[k][tc + 4];
            float a[R];
            #pragma unroll
            for (int q = 0; q < R / 4; q++)
                *(float4*)(a + q * 4) = *(const float4*)&As[k][tr + q * 4];
            #pragma unroll
            for (int i = 0; i < R; i++) {
                u64 ad = dup2(a[i]);
                ffma2(acc2[i][0], ad, b01.x);
                ffma2(acc2[i][1], ad, b01.y);
                ffma2(acc2[i][2], ad, b23.x);
                ffma2(acc2[i][3], ad, b23.y);
            }
        }
    }

    // epilogue
    float4 bb0 = *(const float4*)(bias + n0 + tc);
    float4 bb1 = *(const float4*)(bias + n0 + tc + 4);
    float bv[8] = {bb0.x, bb0.y, bb0.z, bb0.w, bb1.x, bb1.y, bb1.z, bb1.w};
    #pragma unroll
    for (int i = 0; i < R; i++) {
        int row = m0 + tr + i;
        float v[8];
        #pragma unroll
        for (int j = 0; j < 4; j++) unpack2(acc2[i][j], v[2 * j], v[2 * j + 1]);
        #pragma unroll
        for (int c = 0; c < 8; c++) {
            v[c] += bv[c];
            if (MODE == 1)
                v[c] = 0.5f * v[c] * (1.0f + erff(v[c] * 0.70710678118654752f));
        }
        if (MODE == 2) {
            const float* rp = resid + (size_t)row * N + n0 + tc;
            float4 r0 = *(const float4*)(rp);
            float4 r1 = *(const float4*)(rp + 4);
            v[0] += r0.x; v[1] += r0.y; v[2] += r0.z; v[3] += r0.w;
            v[4] += r1.x; v[5] += r1.y; v[6] += r1.z; v[7] += r1.w;
        }
        float* Cp = C + (size_t)row * N + n0 + tc;
        *(float4*)(Cp)     = *(float4*)&v[0];
        *(float4*)(Cp + 4) = *(float4*)&v[4];
    }
}

// ---------------- causal flash attention: 4 threads/query, packed f32x2 ----------------
__global__ __launch_bounds__(256)
void attn_kernel(const float* __restrict__ qkv, float* __restrict__ o)
{
    __shared__ float Ks[64][64];
    __shared__ float Vs[64][64];
    int h = blockIdx.y;
    int qb = gridDim.x - 1 - blockIdx.x;          // heavy blocks first
    int q0 = qb * 64;
    int t = threadIdx.x;
    int qi = q0 + (t >> 2);
    int doff = (t & 3) * 16;

    u64 qd[8];
    {
        const float* qp = qkv + (size_t)qi * (3 * DMODEL) + h * HDIM + doff;
        #pragma unroll
        for (int d = 0; d < 16; d += 4) {
            float4 v = *(const float4*)(qp + d);
            qd[d / 2]     = pack2(v.x * 0.125f, v.y * 0.125f);
            qd[d / 2 + 1] = pack2(v.z * 0.125f, v.w * 0.125f);
        }
    }

    u64 acc2[8];
    #pragma unroll
    for (int d = 0; d < 8; d++) acc2[d] = 0ull;
    float m = -1e30f, l = 0.f;

    for (int kt = 0; kt <= q0; kt += 64) {
        __syncthreads();
        #pragma unroll
        for (int i = 0; i < 4; i++) {
            int lin = t + 256 * i;
            int r = lin >> 4, c4 = (lin & 15) << 2;
            const float* kp = qkv + (size_t)(kt + r) * (3 * DMODEL) + DMODEL + h * HDIM + c4;
            *(float4*)&Ks[r][c4] = *(const float4*)kp;
            *(float4*)&Vs[r][c4] = *(const float4*)(kp + DMODEL);
        }
        __syncthreads();
        int jmax = qi - kt + 1;
        if (jmax > 64) jmax = 64;
        for (int j = 0; j < jmax; j++) {
            const ulonglong2* kp = (const ulonglong2*)&Ks[j][doff];
            ulonglong2 k0 = kp[0], k1 = kp[1], k2 = kp[2], k3 = kp[3];
            u64 s2 = 0ull;
            ffma2(s2, qd[0], k0.x); ffma2(s2, qd[1], k0.y);
            ffma2(s2, qd[2], k1.x); ffma2(s2, qd[3], k1.y);
            ffma2(s2, qd[4], k2.x); ffma2(s2, qd[5], k2.y);
            ffma2(s2, qd[6], k3.x); ffma2(s2, qd[7], k3.y);
            float slo, shi;
            unpack2(s2, slo, shi);
            float s = slo + shi;
            s += __shfl_xor_sync(0xffffffffu, s, 1);
            s += __shfl_xor_sync(0xffffffffu, s, 2);

            const ulonglong2* vp = (const ulonglong2*)&Vs[j][doff];
            ulonglong2 v0 = vp[0], v1 = vp[1], v2 = vp[2], v3 = vp[3];
            if (s <= m) {                     // common path: 1 exp
                float p = __expf(s - m);
                l += p;
                u64 pd = dup2(p);
                ffma2(acc2[0], pd, v0.x); ffma2(acc2[1], pd, v0.y);
                ffma2(acc2[2], pd, v1.x); ffma2(acc2[3], pd, v1.y);
                ffma2(acc2[4], pd, v2.x); ffma2(acc2[5], pd, v2.y);
                ffma2(acc2[6], pd, v3.x); ffma2(acc2[7], pd, v3.y);
            } else {                          // rare: max update
                float al = __expf(m - s);
                l = l * al + 1.f;
                m = s;
                u64 ad = dup2(al);
                ffma2_scale(acc2[0], ad, v0.x); ffma2_scale(acc2[1], ad, v0.y);
                ffma2_scale(acc2[2], ad, v1.x); ffma2_scale(acc2[3], ad, v1.y);
                ffma2_scale(acc2[4], ad, v2.x); ffma2_scale(acc2[5], ad, v2.y);
                ffma2_scale(acc2[6], ad, v3.x); ffma2_scale(acc2[7], ad, v3.y);
            }
        }
    }
    float inv = 1.0f / l;
    float* op = o + (size_t)qi * DMODEL + h * HDIM + doff;
    #pragma unroll
    for (int d = 0; d < 8; d++) {
        float lo, hi;
        unpack2(acc2[d], lo, hi);
        op[2 * d]     = lo * inv;
        op[2 * d + 1] = hi * inv;
    }
}

// ---------------- host orchestration ----------------
extern "C" void kernel_launch(void* const* d_in, const int* in_sizes, int n_in,
                              void* d_out, int out_size)
{
    const int*   idx    = (const int*)  d_in[0];
    const float* temb   = (const float*)d_in[1];
    const float* pe     = (const float*)d_in[2];
    const float* qkv_w  = (const float*)d_in[3];
    const float* qkv_b  = (const float*)d_in[4];
    const float* out_w  = (const float*)d_in[5];
    const float* out_b  = (const float*)d_in[6];
    const float* ln1_s  = (const float*)d_in[7];
    const float* ln1_b  = (const float*)d_in[8];
    const float* ln2_s  = (const float*)d_in[9];
    const float* ln2_b  = (const float*)d_in[10];
    const float* w1     = (const float*)d_in[11];
    const float* b1     = (const float*)d_in[12];
    const float* w2     = (const float*)d_in[13];
    const float* b2     = (const float*)d_in[14];
    float* out = (float*)d_out;

    float *x, *hbuf, *qkvb, *att, *ffn;
    cudaGetSymbolAddress((void**)&x,    g_x);
    cudaGetSymbolAddress((void**)&hbuf, g_h);
    cudaGetSymbolAddress((void**)&qkvb, g_qkv);
    cudaGetSymbolAddress((void**)&att,  g_att);
    cudaGetSymbolAddress((void**)&ffn,  g_ffn);

    embed_kernel<<<S_LEN, 256>>>(idx, temb, pe, x);

    for (int l = 0; l < NLAYER; l++) {
        const float* lqkv_w = qkv_w + (size_t)l * DMODEL * 3 * DMODEL;
        const float* lqkv_b = qkv_b + (size_t)l * 3 * DMODEL;
        const float* lout_w = out_w + (size_t)l * DMODEL * DMODEL;
        const float* lout_b = out_b + (size_t)l * DMODEL;
        const float* lw1    = w1    + (size_t)l * DMODEL * FFN;
        const float* lb1    = b1    + (size_t)l * FFN;
        const float* lw2    = w2    + (size_t)l * FFN * DMODEL;
        const float* lb2    = b2    + (size_t)l * DMODEL;

        // h = LN1(x)
        ln_kernel<<<S_LEN, 256>>>(x, ln1_s + l * DMODEL, ln1_b + l * DMODEL, hbuf);
        // qkv = h @ qkv_w + b         (128x128 tiles, 288 CTAs)
        pgemm_kernel<8, 0><<<dim3(3 * DMODEL / 128, S_LEN / 128), 256>>>(
            hbuf, lqkv_w, lqkv_b, nullptr, qkvb, S_LEN, 3 * DMODEL, DMODEL);
        // attention
        attn_kernel<<<dim3(S_LEN / 64, NHEAD), 256>>>(qkvb, att);
        // x = x + att @ out_w + b     (64x128 tiles, 192 CTAs)
        pgemm_kernel<4, 2><<<dim3(DMODEL / 128, S_LEN / 64), 256>>>(
            att, lout_w, lout_b, x, x, S_LEN, DMODEL, DMODEL);
        // h = LN2(x)
        ln_kernel<<<S_LEN, 256>>>(x, ln2_s + l * DMODEL, ln2_b + l * DMODEL, hbuf);
        // ffn = gelu(h @ w1 + b1)     (128x128 tiles, 384 CTAs)
        pgemm_kernel<8, 1><<<dim3(FFN / 128, S_LEN / 128), 256>>>(
            hbuf, lw1, lb1, nullptr, ffn, S_LEN, FFN, DMODEL);
        // out = x + ffn @ w2 + b2     (64x128 tiles, 192 CTAs)
        float* dst = (l == NLAYER - 1) ? out : x;
        pgemm_kernel<4, 2><<<dim3(DMODEL / 128, S_LEN / 64), 256>>>(
            ffn, lw2, lb2, x, dst, S_LEN, DMODEL, FFN);
    }
}

// round 7
// speedup vs baseline: 2.1147x; 2.1147x over previous
#include <cuda_runtime.h>
#include <cuda_fp16.h>
#include <math.h>
#include <stdint.h>

#define S_LEN 2048
#define DMODEL 768
#define NHEAD 12
#define HDIM 64
#define FFN 3072
#define NLAYER 2

// ---------------- scratch ----------------
__device__ float  g_x  [S_LEN * DMODEL];
__device__ __half g_h  [S_LEN * DMODEL];
__device__ float  g_qkv[S_LEN * 3 * DMODEL];
__device__ __half g_att[S_LEN * DMODEL];
__device__ __half g_ffn[S_LEN * FFN];
#define WT_LAYER 7077888
__device__ __half g_wt [NLAYER * WT_LAYER];

// ---------------- ptx helpers (baseline ISA only) ----------------
__device__ __forceinline__ uint32_t smem_u32(const void* p) {
    uint32_t a;
    asm("{ .reg .u64 t; cvta.to.shared.u64 t, %1; cvt.u32.u64 %0, t; }" : "=r"(a) : "l"(p));
    return a;
}
__device__ __forceinline__ void cp16(uint32_t s, const void* g) {
    asm volatile("cp.async.cg.shared.global [%0], [%1], 16;" :: "r"(s), "l"(g));
}
__device__ __forceinline__ void cp_commit() { asm volatile("cp.async.commit_group;" ::: "memory"); }
__device__ __forceinline__ void cp_wait1()  { asm volatile("cp.async.wait_group 1;" ::: "memory"); }
__device__ __forceinline__ void cp_wait0()  { asm volatile("cp.async.wait_group 0;" ::: "memory"); }

__device__ __forceinline__ void ldsm4(uint32_t* r, uint32_t addr) {
    asm volatile("ldmatrix.sync.aligned.m8n8.x4.shared.b16 {%0,%1,%2,%3}, [%4];"
        : "=r"(r[0]), "=r"(r[1]), "=r"(r[2]), "=r"(r[3]) : "r"(addr));
}
__device__ __forceinline__ void mma16816(float* c, const uint32_t* a, const uint32_t* b) {
    asm volatile(
        "mma.sync.aligned.m16n8k16.row.col.f32.f16.f16.f32 "
        "{%0,%1,%2,%3}, {%4,%5,%6,%7}, {%8,%9}, {%0,%1,%2,%3};"
        : "+f"(c[0]), "+f"(c[1]), "+f"(c[2]), "+f"(c[3])
        : "r"(a[0]), "r"(a[1]), "r"(a[2]), "r"(a[3]), "r"(b[0]), "r"(b[1]));
}

// ---------------- fused weight transpose + fp16 convert ----------------
// All 8 matrices (2 layers x {qkv_w, out_w, w1, w2}), W[K,N] -> Wt[N,K] fp16.
#define OQKV 0
#define OOUT 1769472
#define OW1  2359296
#define OW2  4718592
__global__ __launch_bounds__(256)
void wconv_all_kernel(const float* __restrict__ qkv_w, const float* __restrict__ out_w,
                      const float* __restrict__ w1, const float* __restrict__ w2,
                      __half* __restrict__ wt)
{
    __shared__ float t[32][33];
    int bid = blockIdx.x;
    int layer = bid / 6912;
    int tIdx = bid % 6912;
    const float* W;
    __half* D;
    int K, N, nx;
    __half* wl = wt + (size_t)layer * WT_LAYER;
    if (tIdx < 1728)      { W = qkv_w + (size_t)layer * 768 * 2304; D = wl + OQKV; K = 768;  N = 2304; nx = 72; }
    else if (tIdx < 2304) { tIdx -= 1728; W = out_w + (size_t)layer * 768 * 768;  D = wl + OOUT; K = 768;  N = 768;  nx = 24; }
    else if (tIdx < 4608) { tIdx -= 2304; W = w1 + (size_t)layer * 768 * 3072;    D = wl + OW1;  K = 768;  N = 3072; nx = 96; }
    else                  { tIdx -= 4608; W = w2 + (size_t)layer * 3072 * 768;    D = wl + OW2;  K = 3072; N = 768;  nx = 24; }
    int n0 = (tIdx % nx) * 32, k0 = (tIdx / nx) * 32;
    int tx = threadIdx.x, ty = threadIdx.y;
    #pragma unroll
    for (int i = 0; i < 32; i += 8)
        t[ty + i][tx] = W[(size_t)(k0 + ty + i) * N + n0 + tx];
    __syncthreads();
    #pragma unroll
    for (int i = 0; i < 32; i += 8)
        D[(size_t)(n0 + ty + i) * K + k0 + tx] = __float2half(t[tx][ty + i]);
}

// ---------------- embed ----------------
__global__ __launch_bounds__(256)
void embed_kernel(const int* __restrict__ idx, const float* __restrict__ emb,
                  const float* __restrict__ pe, float* __restrict__ x)
{
    int t = blockIdx.x;
    int tok = idx[t];
    const float* ep = emb + (size_t)tok * DMODEL;
    const float* pp = pe + (size_t)t * DMODEL;
    float* xp = x + (size_t)t * DMODEL;
    for (int d = threadIdx.x; d < DMODEL; d += 256)
        xp[d] = ep[d] + pp[d];
}

// ---------------- layernorm (fp32 in, fp16 out) ----------------
__device__ __forceinline__ float block_reduce_sum(float v, float* red)
{
    #pragma unroll
    for (int o = 16; o > 0; o >>= 1) v += __shfl_xor_sync(0xffffffffu, v, o);
    __syncthreads();
    if ((threadIdx.x & 31) == 0) red[threadIdx.x >> 5] = v;
    __syncthreads();
    float t = 0.f;
    #pragma unroll
    for (int i = 0; i < 8; i++) t += red[i];
    return t;
}

__global__ __launch_bounds__(256)
void ln_kernel(const float* __restrict__ x, const float* __restrict__ s,
               const float* __restrict__ b, __half* __restrict__ o)
{
    __shared__ float red[8];
    int row = blockIdx.x;
    int tid = threadIdx.x;
    const float* xp = x + (size_t)row * DMODEL;
    float v0 = xp[tid], v1 = xp[tid + 256], v2 = xp[tid + 512];
    float mean = block_reduce_sum(v0 + v1 + v2, red) * (1.0f / DMODEL);
    float d0 = v0 - mean, d1 = v1 - mean, d2 = v2 - mean;
    float var = block_reduce_sum(d0 * d0 + d1 * d1 + d2 * d2, red) * (1.0f / DMODEL);
    float r = rsqrtf(var + 1e-5f);
    __half* op = o + (size_t)row * DMODEL;
    op[tid]       = __float2half(d0 * r * s[tid]       + b[tid]);
    op[tid + 256] = __float2half(d1 * r * s[tid + 256] + b[tid + 256]);
    op[tid + 512] = __float2half(d2 * r * s[tid + 512] + b[tid + 512]);
}

// ---------------- fp16 HMMA GEMM: C[M,N] = A[M,K] @ Bt[N,K]^T ----------------
// Tile 64 x BN, warp tile 32x32 (warp grid 2 x BN/32), threads = 2*BN.
// k-slab 64 halves (128B rows), double-buffered cp.async, ldmatrix fragments.
// MODE 0: +bias (float out)  MODE 1: gelu(+bias) (half out)  MODE 2: +bias+resid (float out)
#define SWC(c, r) ((((c) ^ ((r) & 7))) << 4)
template<int BN, int MODE>
__global__ __launch_bounds__(2 * BN)
void hgemm_kernel(const __half* __restrict__ A, const __half* __restrict__ Bt,
                  const float* __restrict__ bias, const float* __restrict__ resid,
                  void* __restrict__ Cv, int M, int N, int K)
{
    extern __shared__ __align__(1024) char smem[];
    constexpr int THR = 2 * BN;
    constexpr int ABYTES = 64 * 128;            // 8KB
    constexpr int STG = (64 + BN) * 128;        // per stage

    uint32_t sb = smem_u32(smem);
    int tid = threadIdx.x, lane = tid & 31, warp = tid >> 5;
    int warp_m = warp & 1, warp_n = warp >> 1;
    int m0 = blockIdx.y * 64, n0 = blockIdx.x * BN;
    int mbase = warp_m * 32, nbase = warp_n * 32;

    const __half* Ag0 = A + (size_t)m0 * K;
    const __half* Bg0 = Bt + (size_t)n0 * K;
    int nslab = K >> 6;

    auto load_slab = [&](int s, int b) {
        uint32_t ab = sb + b * STG;
        uint32_t bb = ab + ABYTES;
        const __half* Ap = Ag0 + s * 64;
        const __half* Bp = Bg0 + s * 64;
        #pragma unroll
        for (int i = 0; i < 512 / THR; i++) {
            int idx = tid + THR * i;
            int r = idx >> 3, c = idx & 7;
            cp16(ab + r * 128 + SWC(c, r), Ap + (size_t)r * K + c * 8);
        }
        #pragma unroll
        for (int i = 0; i < (8 * BN) / THR; i++) {
            int idx = tid + THR * i;
            int r = idx >> 3, c = idx & 7;
            cp16(bb + r * 128 + SWC(c, r), Bp + (size_t)r * K + c * 8);
        }
        cp_commit();
    };

    float acc[2][4][4];
    #pragma unroll
    for (int mt = 0; mt < 2; mt++)
        #pragma unroll
        for (int nt = 0; nt < 4; nt++)
            #pragma unroll
            for (int i = 0; i < 4; i++) acc[mt][nt][i] = 0.f;

    load_slab(0, 0);

    int lrA = lane & 15, lcA = lane >> 4;
    int lrB = ((lane >> 4) << 3) + (lane & 7), lcB = (lane >> 3) & 1;

    for (int s = 0; s < nslab; s++) {
        if (s + 1 < nslab) { load_slab(s + 1, (s + 1) & 1); cp_wait1(); }
        else               { cp_wait0(); }
        __syncthreads();

        uint32_t ab = sb + (s & 1) * STG;
        uint32_t bb = ab + ABYTES;

        #pragma unroll
        for (int k = 0; k < 4; k++) {
            uint32_t a[2][4], bq[2][4];
            #pragma unroll
            for (int mt = 0; mt < 2; mt++) {
                int r = mbase + mt * 16 + lrA;
                int c = k * 2 + lcA;
                ldsm4(a[mt], ab + r * 128 + SWC(c, r));
            }
            #pragma unroll
            for (int p = 0; p < 2; p++) {
                int r = nbase + p * 16 + lrB;
                int c = k * 2 + lcB;
                ldsm4(bq[p], bb + r * 128 + SWC(c, r));
            }
            #pragma unroll
            for (int mt = 0; mt < 2; mt++)
                #pragma unroll
                for (int nt = 0; nt < 4; nt++)
                    mma16816(acc[mt][nt], a[mt], bq[nt >> 1] + 2 * (nt & 1));
        }
        __syncthreads();
    }

    // epilogue (fragment: rows lane/4, lane/4+8; cols 2*(lane%4)+{0,1})
    int row4 = lane >> 2, col2 = (lane & 3) * 2;
    #pragma unroll
    for (int mt = 0; mt < 2; mt++) {
        #pragma unroll
        for (int nt = 0; nt < 4; nt++) {
            int r0 = m0 + mbase + mt * 16 + row4;
            int cc = n0 + nbase + nt * 8 + col2;
            float2 bb = *(const float2*)(bias + cc);
            float v0 = acc[mt][nt][0] + bb.x, v1 = acc[mt][nt][1] + bb.y;
            float v2 = acc[mt][nt][2] + bb.x, v3 = acc[mt][nt][3] + bb.y;
            if (MODE == 1) {
                v0 = 0.5f * v0 * (1.0f + erff(v0 * 0.70710678118654752f));
                v1 = 0.5f * v1 * (1.0f + erff(v1 * 0.70710678118654752f));
                v2 = 0.5f * v2 * (1.0f + erff(v2 * 0.70710678118654752f));
                v3 = 0.5f * v3 * (1.0f + erff(v3 * 0.70710678118654752f));
            }
            if (MODE == 2) {
                float2 ra = *(const float2*)(resid + (size_t)r0 * N + cc);
                float2 rb = *(const float2*)(resid + (size_t)(r0 + 8) * N + cc);
                v0 += ra.x; v1 += ra.y; v2 += rb.x; v3 += rb.y;
            }
            if (MODE == 1) {
                __half* Cp = (__half*)Cv;
                *(__half2*)(Cp + (size_t)r0 * N + cc)       = __floats2half2_rn(v0, v1);
                *(__half2*)(Cp + (size_t)(r0 + 8) * N + cc) = __floats2half2_rn(v2, v3);
            } else {
                float* Cp = (float*)Cv;
                float2 o0 = {v0, v1}, o1 = {v2, v3};
                *(float2*)(Cp + (size_t)r0 * N + cc) = o0;
                *(float2*)(Cp + (size_t)(r0 + 8) * N + cc) = o1;
            }
        }
    }
}

// ---------------- causal flash attention: 32 queries/CTA, 4 threads/query ----------------
__global__ __launch_bounds__(128)
void attn_kernel(const float* __restrict__ qkv, __half* __restrict__ o)
{
    __shared__ float Ks[64][64];
    __shared__ float Vs[64][64];
    int h = blockIdx.y;
    int qb = gridDim.x - 1 - blockIdx.x;          // heavy blocks first
    int q0 = qb * 32;
    int t = threadIdx.x;
    int qi = q0 + (t >> 2);
    int doff = (t & 3) * 16;

    float q[16];
    const float* qp = qkv + (size_t)qi * (3 * DMODEL) + h * HDIM + doff;
    #pragma unroll
    for (int d = 0; d < 16; d += 4) {
        float4 v = *(const float4*)(qp + d);
        q[d] = v.x * 0.125f; q[d + 1] = v.y * 0.125f;
        q[d + 2] = v.z * 0.125f; q[d + 3] = v.w * 0.125f;
    }

    float acc[16];
    #pragma unroll
    for (int d = 0; d < 16; d++) acc[d] = 0.f;
    float m = -1e30f, l = 0.f;

    for (int kt = 0; kt <= q0; kt += 64) {
        __syncthreads();
        #pragma unroll
        for (int i = 0; i < 8; i++) {
            int lin = t + 128 * i;
            int r = lin >> 4, c4 = (lin & 15) << 2;
            int rr = kt + r; if (rr > S_LEN - 1) rr = S_LEN - 1;   // clamp (masked anyway)
            const float* kp = qkv + (size_t)rr * (3 * DMODEL) + DMODEL + h * HDIM + c4;
            *(float4*)&Ks[r][c4] = *(const float4*)kp;
            *(float4*)&Vs[r][c4] = *(const float4*)(kp + DMODEL);
        }
        __syncthreads();
        int jmax = qi - kt + 1;
        if (jmax > 64) jmax = 64;
        for (int j = 0; j < jmax; j++) {
            float s = 0.f;
            #pragma unroll
            for (int d = 0; d < 16; d += 4) {
                float4 kv = *(const float4*)&Ks[j][doff + d];
                s = fmaf(q[d], kv.x, s); s = fmaf(q[d + 1], kv.y, s);
                s = fmaf(q[d + 2], kv.z, s); s = fmaf(q[d + 3], kv.w, s);
            }
            s += __shfl_xor_sync(0xffffffffu, s, 1);
            s += __shfl_xor_sync(0xffffffffu, s, 2);
            if (s <= m) {
                float p = __expf(s - m);
                l += p;
                #pragma unroll
                for (int d = 0; d < 16; d += 4) {
                    float4 vv = *(const float4*)&Vs[j][doff + d];
                    acc[d]     = fmaf(p, vv.x, acc[d]);
                    acc[d + 1] = fmaf(p, vv.y, acc[d + 1]);
                    acc[d + 2] = fmaf(p, vv.z, acc[d + 2]);
                    acc[d + 3] = fmaf(p, vv.w, acc[d + 3]);
                }
            } else {
                float al = __expf(m - s);
                l = l * al + 1.f;
                m = s;
                #pragma unroll
                for (int d = 0; d < 16; d += 4) {
                    float4 vv = *(const float4*)&Vs[j][doff + d];
                    acc[d]     = fmaf(acc[d], al, vv.x);
                    acc[d + 1] = fmaf(acc[d + 1], al, vv.y);
                    acc[d + 2] = fmaf(acc[d + 2], al, vv.z);
                    acc[d + 3] = fmaf(acc[d + 3], al, vv.w);
                }
            }
        }
    }
    float inv = 1.0f / l;
    __half2* op = (__half2*)(o + (size_t)qi * DMODEL + h * HDIM + doff);
    #pragma unroll
    for (int d = 0; d < 8; d++)
        op[d] = __floats2half2_rn(acc[2 * d] * inv, acc[2 * d + 1] * inv);
}

// ---------------- host orchestration ----------------
extern "C" void kernel_launch(void* const* d_in, const int* in_sizes, int n_in,
                              void* d_out, int out_size)
{
    const int*   idx    = (const int*)  d_in[0];
    const float* temb   = (const float*)d_in[1];
    const float* pe     = (const float*)d_in[2];
    const float* qkv_w  = (const float*)d_in[3];
    const float* qkv_b  = (const float*)d_in[4];
    const float* out_w  = (const float*)d_in[5];
    const float* out_b  = (const float*)d_in[6];
    const float* ln1_s  = (const float*)d_in[7];
    const float* ln1_b  = (const float*)d_in[8];
    const float* ln2_s  = (const float*)d_in[9];
    const float* ln2_b  = (const float*)d_in[10];
    const float* w1     = (const float*)d_in[11];
    const float* b1     = (const float*)d_in[12];
    const float* w2     = (const float*)d_in[13];
    const float* b2     = (const float*)d_in[14];
    float* out = (float*)d_out;

    float *x, *qkvb;
    __half *hbuf, *att, *ffn, *wt;
    cudaGetSymbolAddress((void**)&x,    g_x);
    cudaGetSymbolAddress((void**)&hbuf, g_h);
    cudaGetSymbolAddress((void**)&qkvb, g_qkv);
    cudaGetSymbolAddress((void**)&att,  g_att);
    cudaGetSymbolAddress((void**)&ffn,  g_ffn);
    cudaGetSymbolAddress((void**)&wt,   g_wt);

    constexpr int SMB128 = (64 + 128) * 128 * 2;   // 49152
    constexpr int SMB64  = (64 + 64) * 128 * 2;    // 32768
    cudaFuncSetAttribute(hgemm_kernel<128, 0>, cudaFuncAttributeMaxDynamicSharedMemorySize, SMB128);
    cudaFuncSetAttribute(hgemm_kernel<128, 1>, cudaFuncAttributeMaxDynamicSharedMemorySize, SMB128);
    cudaFuncSetAttribute(hgemm_kernel<64, 2>,  cudaFuncAttributeMaxDynamicSharedMemorySize, SMB64);

    // single fused weight prepass (1 launch)
    wconv_all_kernel<<<2 * 6912, dim3(32, 8)>>>(qkv_w, out_w, w1, w2, wt);

    embed_kernel<<<S_LEN, 256>>>(idx, temb, pe, x);

    for (int l = 0; l < NLAYER; l++) {
        __half* wl = wt + (size_t)l * WT_LAYER;
        const float* lqkv_b = qkv_b + (size_t)l * 3 * DMODEL;
        const float* lout_b = out_b + (size_t)l * DMODEL;
        const float* lb1    = b1 + (size_t)l * FFN;
        const float* lb2    = b2 + (size_t)l * DMODEL;

        ln_kernel<<<S_LEN, 256>>>(x, ln1_s + l * DMODEL, ln1_b + l * DMODEL, hbuf);
        hgemm_kernel<128, 0><<<dim3(3 * DMODEL / 128, S_LEN / 64), 256, SMB128>>>(
            hbuf, wl + OQKV, lqkv_b, nullptr, qkvb, S_LEN, 3 * DMODEL, DMODEL);
        attn_kernel<<<dim3(S_LEN / 32, NHEAD), 128>>>(qkvb, att);
        hgemm_kernel<64, 2><<<dim3(DMODEL / 64, S_LEN / 64), 128, SMB64>>>(
            att, wl + OOUT, lout_b, x, x, S_LEN, DMODEL, DMODEL);
        ln_kernel<<<S_LEN, 256>>>(x, ln2_s + l * DMODEL, ln2_b + l * DMODEL, hbuf);
        hgemm_kernel<128, 1><<<dim3(FFN / 128, S_LEN / 64), 256, SMB128>>>(
            hbuf, wl + OW1, lb1, nullptr, ffn, S_LEN, FFN, DMODEL);
        float* dst = (l == NLAYER - 1) ? out : x;
        hgemm_kernel<64, 2><<<dim3(DMODEL / 64, S_LEN / 64), 128, SMB64>>>(
            ffn, wl + OW2, lb2, x, dst, S_LEN, DMODEL, FFN);
    }
}

// round 9
// speedup vs baseline: 13.8332x; 6.5415x over previous
#include <cuda_runtime.h>
#include <cuda_fp16.h>
#include <math.h>
#include <stdint.h>

#define S_LEN 2048
#define DMODEL 768
#define NHEAD 12
#define HDIM 64
#define FFN 3072
#define NLAYER 2

// ---------------- scratch ----------------
__device__ float  g_x  [S_LEN * DMODEL];
__device__ __half g_h  [S_LEN * DMODEL];
__device__ __half g_qkv[S_LEN * 3 * DMODEL];
__device__ __half g_att[S_LEN * DMODEL];
__device__ __half g_ffn[S_LEN * FFN];
#define WT_LAYER 7077888
__device__ __half g_wt [NLAYER * WT_LAYER];

// ---------------- ptx helpers (baseline ISA only) ----------------
__device__ __forceinline__ uint32_t smem_u32(const void* p) {
    uint32_t a;
    asm("{ .reg .u64 t; cvta.to.shared.u64 t, %1; cvt.u32.u64 %0, t; }" : "=r"(a) : "l"(p));
    return a;
}
__device__ __forceinline__ void cp16(uint32_t s, const void* g) {
    asm volatile("cp.async.cg.shared.global [%0], [%1], 16;" :: "r"(s), "l"(g));
}
__device__ __forceinline__ void cp_commit() { asm volatile("cp.async.commit_group;" ::: "memory"); }
__device__ __forceinline__ void cp_wait1()  { asm volatile("cp.async.wait_group 1;" ::: "memory"); }
__device__ __forceinline__ void cp_wait0()  { asm volatile("cp.async.wait_group 0;" ::: "memory"); }

__device__ __forceinline__ void ldsm4(uint32_t* r, uint32_t addr) {
    asm volatile("ldmatrix.sync.aligned.m8n8.x4.shared.b16 {%0,%1,%2,%3}, [%4];"
        : "=r"(r[0]), "=r"(r[1]), "=r"(r[2]), "=r"(r[3]) : "r"(addr));
}
__device__ __forceinline__ void ldsm4t(uint32_t* r, uint32_t addr) {
    asm volatile("ldmatrix.sync.aligned.m8n8.x4.trans.shared.b16 {%0,%1,%2,%3}, [%4];"
        : "=r"(r[0]), "=r"(r[1]), "=r"(r[2]), "=r"(r[3]) : "r"(addr));
}
__device__ __forceinline__ void mma16816(float* c, const uint32_t* a, const uint32_t* b) {
    asm volatile(
        "mma.sync.aligned.m16n8k16.row.col.f32.f16.f16.f32 "
        "{%0,%1,%2,%3}, {%4,%5,%6,%7}, {%8,%9}, {%0,%1,%2,%3};"
        : "+f"(c[0]), "+f"(c[1]), "+f"(c[2]), "+f"(c[3])
        : "r"(a[0]), "r"(a[1]), "r"(a[2]), "r"(a[3]), "r"(b[0]), "r"(b[1]));
}

// ---------------- fused weight transpose + fp16 convert ----------------
#define OQKV 0
#define OOUT 1769472
#define OW1  2359296
#define OW2  4718592
__global__ __launch_bounds__(256)
void wconv_all_kernel(const float* __restrict__ qkv_w, const float* __restrict__ out_w,
                      const float* __restrict__ w1, const float* __restrict__ w2,
                      __half* __restrict__ wt)
{
    __shared__ float t[32][33];
    int bid = blockIdx.x;
    int layer = bid / 6912;
    int tIdx = bid % 6912;
    const float* W;
    __half* D;
    int K, N, nx;
    __half* wl = wt + (size_t)layer * WT_LAYER;
    if (tIdx < 1728)      { W = qkv_w + (size_t)layer * 768 * 2304; D = wl + OQKV; K = 768;  N = 2304; nx = 72; }
    else if (tIdx < 2304) { tIdx -= 1728; W = out_w + (size_t)layer * 768 * 768;  D = wl + OOUT; K = 768;  N = 768;  nx = 24; }
    else if (tIdx < 4608) { tIdx -= 2304; W = w1 + (size_t)layer * 768 * 3072;    D = wl + OW1;  K = 768;  N = 3072; nx = 96; }
    else                  { tIdx -= 4608; W = w2 + (size_t)layer * 3072 * 768;    D = wl + OW2;  K = 3072; N = 768;  nx = 24; }
    int n0 = (tIdx % nx) * 32, k0 = (tIdx / nx) * 32;
    int tx = threadIdx.x, ty = threadIdx.y;
    #pragma unroll
    for (int i = 0; i < 32; i += 8)
        t[ty + i][tx] = W[(size_t)(k0 + ty + i) * N + n0 + tx];
    __syncthreads();
    #pragma unroll
    for (int i = 0; i < 32; i += 8)
        D[(size_t)(n0 + ty + i) * K + k0 + tx] = __float2half(t[tx][ty + i]);
}

// ---------------- embed ----------------
__global__ __launch_bounds__(256)
void embed_kernel(const int* __restrict__ idx, const float* __restrict__ emb,
                  const float* __restrict__ pe, float* __restrict__ x)
{
    int t = blockIdx.x;
    int tok = idx[t];
    const float* ep = emb + (size_t)tok * DMODEL;
    const float* pp = pe + (size_t)t * DMODEL;
    float* xp = x + (size_t)t * DMODEL;
    for (int d = threadIdx.x; d < DMODEL; d += 256)
        xp[d] = ep[d] + pp[d];
}

// ---------------- layernorm (fp32 in, fp16 out) ----------------
__device__ __forceinline__ float block_reduce_sum(float v, float* red)
{
    #pragma unroll
    for (int o = 16; o > 0; o >>= 1) v += __shfl_xor_sync(0xffffffffu, v, o);
    __syncthreads();
    if ((threadIdx.x & 31) == 0) red[threadIdx.x >> 5] = v;
    __syncthreads();
    float t = 0.f;
    #pragma unroll
    for (int i = 0; i < 8; i++) t += red[i];
    return t;
}

__global__ __launch_bounds__(256)
void ln_kernel(const float* __restrict__ x, const float* __restrict__ s,
               const float* __restrict__ b, __half* __restrict__ o)
{
    __shared__ float red[8];
    int row = blockIdx.x;
    int tid = threadIdx.x;
    const float* xp = x + (size_t)row * DMODEL;
    float v0 = xp[tid], v1 = xp[tid + 256], v2 = xp[tid + 512];
    float mean = block_reduce_sum(v0 + v1 + v2, red) * (1.0f / DMODEL);
    float d0 = v0 - mean, d1 = v1 - mean, d2 = v2 - mean;
    float var = block_reduce_sum(d0 * d0 + d1 * d1 + d2 * d2, red) * (1.0f / DMODEL);
    float r = rsqrtf(var + 1e-5f);
    __half* op = o + (size_t)row * DMODEL;
    op[tid]       = __float2half(d0 * r * s[tid]       + b[tid]);
    op[tid + 256] = __float2half(d1 * r * s[tid + 256] + b[tid + 256]);
    op[tid + 512] = __float2half(d2 * r * s[tid + 512] + b[tid + 512]);
}

// ---------------- fp16 HMMA GEMM: C[M,N] = A[M,K] @ Bt[N,K]^T ----------------
// Tile 64 x BN, warp tile 32x32, threads = 2*BN, double-buffered cp.async.
// MODE 0: +bias (half out)  MODE 1: gelu(+bias) (half out)  MODE 2: +bias+resid (float out)
#define SWC(c, r) ((((c) ^ ((r) & 7))) << 4)
template<int BN, int MODE>
__global__ __launch_bounds__(2 * BN)
void hgemm_kernel(const __half* __restrict__ A, const __half* __restrict__ Bt,
                  const float* __restrict__ bias, const float* __restrict__ resid,
                  void* __restrict__ Cv, int M, int N, int K)
{
    extern __shared__ __align__(1024) char smem[];
    constexpr int THR = 2 * BN;
    constexpr int ABYTES = 64 * 128;
    constexpr int STG = (64 + BN) * 128;

    uint32_t sb = smem_u32(smem);
    int tid = threadIdx.x, lane = tid & 31, warp = tid >> 5;
    int warp_m = warp & 1, warp_n = warp >> 1;
    int m0 = blockIdx.y * 64, n0 = blockIdx.x * BN;
    int mbase = warp_m * 32, nbase = warp_n * 32;

    const __half* Ag0 = A + (size_t)m0 * K;
    const __half* Bg0 = Bt + (size_t)n0 * K;
    int nslab = K >> 6;

    auto load_slab = [&](int s, int b) {
        uint32_t ab = sb + b * STG;
        uint32_t bb = ab + ABYTES;
        const __half* Ap = Ag0 + s * 64;
        const __half* Bp = Bg0 + s * 64;
        #pragma unroll
        for (int i = 0; i < 512 / THR; i++) {
            int idx = tid + THR * i;
            int r = idx >> 3, c = idx & 7;
            cp16(ab + r * 128 + SWC(c, r), Ap + (size_t)r * K + c * 8);
        }
        #pragma unroll
        for (int i = 0; i < (8 * BN) / THR; i++) {
            int idx = tid + THR * i;
            int r = idx >> 3, c = idx & 7;
            cp16(bb + r * 128 + SWC(c, r), Bp + (size_t)r * K + c * 8);
        }
        cp_commit();
    };

    float acc[2][4][4];
    #pragma unroll
    for (int mt = 0; mt < 2; mt++)
        #pragma unroll
        for (int nt = 0; nt < 4; nt++)
            #pragma unroll
            for (int i = 0; i < 4; i++) acc[mt][nt][i] = 0.f;

    load_slab(0, 0);

    int lrA = lane & 15, lcA = lane >> 4;
    int lrB = ((lane >> 4) << 3) + (lane & 7), lcB = (lane >> 3) & 1;

    for (int s = 0; s < nslab; s++) {
        if (s + 1 < nslab) { load_slab(s + 1, (s + 1) & 1); cp_wait1(); }
        else               { cp_wait0(); }
        __syncthreads();

        uint32_t ab = sb + (s & 1) * STG;
        uint32_t bb = ab + ABYTES;

        #pragma unroll
        for (int k = 0; k < 4; k++) {
            uint32_t a[2][4], bq[2][4];
            #pragma unroll
            for (int mt = 0; mt < 2; mt++) {
                int r = mbase + mt * 16 + lrA;
                int c = k * 2 + lcA;
                ldsm4(a[mt], ab + r * 128 + SWC(c, r));
            }
            #pragma unroll
            for (int p = 0; p < 2; p++) {
                int r = nbase + p * 16 + lrB;
                int c = k * 2 + lcB;
                ldsm4(bq[p], bb + r * 128 + SWC(c, r));
            }
            #pragma unroll
            for (int mt = 0; mt < 2; mt++)
                #pragma unroll
                for (int nt = 0; nt < 4; nt++)
                    mma16816(acc[mt][nt], a[mt], bq[nt >> 1] + 2 * (nt & 1));
        }
        __syncthreads();
    }

    int row4 = lane >> 2, col2 = (lane & 3) * 2;
    #pragma unroll
    for (int mt = 0; mt < 2; mt++) {
        #pragma unroll
        for (int nt = 0; nt < 4; nt++) {
            int r0 = m0 + mbase + mt * 16 + row4;
            int cc = n0 + nbase + nt * 8 + col2;
            float2 bb = *(const float2*)(bias + cc);
            float v0 = acc[mt][nt][0] + bb.x, v1 = acc[mt][nt][1] + bb.y;
            float v2 = acc[mt][nt][2] + bb.x, v3 = acc[mt][nt][3] + bb.y;
            if (MODE == 1) {
                v0 = 0.5f * v0 * (1.0f + erff(v0 * 0.70710678118654752f));
                v1 = 0.5f * v1 * (1.0f + erff(v1 * 0.70710678118654752f));
                v2 = 0.5f * v2 * (1.0f + erff(v2 * 0.70710678118654752f));
                v3 = 0.5f * v3 * (1.0f + erff(v3 * 0.70710678118654752f));
            }
            if (MODE == 2) {
                float2 ra = *(const float2*)(resid + (size_t)r0 * N + cc);
                float2 rb = *(const float2*)(resid + (size_t)(r0 + 8) * N + cc);
                v0 += ra.x; v1 += ra.y; v2 += rb.x; v3 += rb.y;
                float* Cp = (float*)Cv;
                float2 o0 = {v0, v1}, o1 = {v2, v3};
                *(float2*)(Cp + (size_t)r0 * N + cc) = o0;
                *(float2*)(Cp + (size_t)(r0 + 8) * N + cc) = o1;
            } else {
                __half* Cp = (__half*)Cv;
                *(__half2*)(Cp + (size_t)r0 * N + cc)       = __floats2half2_rn(v0, v1);
                *(__half2*)(Cp + (size_t)(r0 + 8) * N + cc) = __floats2half2_rn(v2, v3);
            }
        }
    }
}

// ---------------- tensor-core causal flash attention ----------------
// CTA: 64 queries x 1 head, 4 warps (16 query rows each). fp16 in/out, fp32 softmax/accum.
// smem: Q [0,8K); stage st in {0,1}: K at 8K+st*16K, V at +8K.
__global__ __launch_bounds__(128)
void fattn_kernel(const __half* __restrict__ qkv, __half* __restrict__ o)
{
    extern __shared__ __align__(1024) char smem[];
    uint32_t sb = smem_u32(smem);
    int h = blockIdx.y;
    int qblk = gridDim.x - 1 - blockIdx.x;          // heavy blocks first
    int q0 = qblk * 64;
    int tid = threadIdx.x, lane = tid & 31, warp = tid >> 5;
    int mbase = warp * 16;
    int ntile = qblk + 1;

    auto loadKV = [&](int kt, int st) {
        uint32_t kb = sb + 8192 + st * 16384;
        uint32_t vb = kb + 8192;
        #pragma unroll
        for (int i = 0; i < 4; i++) {
            int idx = tid + 128 * i;
            int r = idx >> 3, c = idx & 7;
            const __half* kp = qkv + (size_t)(kt + r) * 2304 + 768 + h * 64 + c * 8;
            cp16(kb + r * 128 + SWC(c, r), kp);
            cp16(vb + r * 128 + SWC(c, r), kp + 768);
        }
        cp_commit();
    };

    // Q tile + first KV stage in one cp.async group
    #pragma unroll
    for (int i = 0; i < 4; i++) {
        int idx = tid + 128 * i;
        int r = idx >> 3, c = idx & 7;
        cp16(sb + r * 128 + SWC(c, r), qkv + (size_t)(q0 + r) * 2304 + h * 64 + c * 8);
    }
    loadKV(0, 0);

    uint32_t qf[4][4];
    float oacc[8][4];
    #pragma unroll
    for (int nt = 0; nt < 8; nt++)
        #pragma unroll
        for (int i = 0; i < 4; i++) oacc[nt][i] = 0.f;
    float m0 = -1e30f, m1 = -1e30f, l0 = 0.f, l1 = 0.f;

    int lrA = lane & 15, lcA = lane >> 4;
    int lrB = ((lane >> 4) << 3) + (lane & 7), lcB = (lane >> 3) & 1;
    int qrow0 = q0 + mbase + (lane >> 2);           // this thread's row0 query index

    for (int it = 0; it < ntile; it++) {
        if (it + 1 < ntile) { loadKV((it + 1) * 64, (it + 1) & 1); cp_wait1(); }
        else                { cp_wait0(); }
        __syncthreads();
        if (it == 0) {
            #pragma unroll
            for (int ks = 0; ks < 4; ks++) {
                int r = mbase + lrA, c = ks * 2 + lcA;
                ldsm4(qf[ks], sb + r * 128 + SWC(c, r));
            }
        }
        uint32_t kb = sb + 8192 + (it & 1) * 16384;
        uint32_t vb = kb + 8192;

        // ---- scores = Q @ K^T ----
        float sc[8][4];
        #pragma unroll
        for (int nt = 0; nt < 8; nt++)
            #pragma unroll
            for (int i = 0; i < 4; i++) sc[nt][i] = 0.f;
        #pragma unroll
        for (int ks = 0; ks < 4; ks++) {
            uint32_t kf[4][4];
            #pragma unroll
            for (int p = 0; p < 4; p++) {
                int r = p * 16 + lrB, c = ks * 2 + lcB;
                ldsm4(kf[p], kb + r * 128 + SWC(c, r));
            }
            #pragma unroll
            for (int nt = 0; nt < 8; nt++)
                mma16816(sc[nt], qf[ks], kf[nt >> 1] + 2 * (nt & 1));
        }

        // ---- scale + causal mask (only final tile is diagonal) ----
        if (it == ntile - 1) {
            #pragma unroll
            for (int nt = 0; nt < 8; nt++) {
                int kc = it * 64 + nt * 8 + (lane & 3) * 2;
                sc[nt][0] = (kc     <= qrow0)     ? sc[nt][0] * 0.125f : -1e30f;
                sc[nt][1] = (kc + 1 <= qrow0)     ? sc[nt][1] * 0.125f : -1e30f;
                sc[nt][2] = (kc     <= qrow0 + 8) ? sc[nt][2] * 0.125f : -1e30f;
                sc[nt][3] = (kc + 1 <= qrow0 + 8) ? sc[nt][3] * 0.125f : -1e30f;
            }
        } else {
            #pragma unroll
            for (int nt = 0; nt < 8; nt++) {
                sc[nt][0] *= 0.125f; sc[nt][1] *= 0.125f;
                sc[nt][2] *= 0.125f; sc[nt][3] *= 0.125f;
            }
        }

        // ---- online softmax (tile-granular) ----
        float mx0 = sc[0][0], mx1 = sc[0][2];
        #pragma unroll
        for (int nt = 0; nt < 8; nt++) {
            mx0 = fmaxf(mx0, fmaxf(sc[nt][0], sc[nt][1]));
            mx1 = fmaxf(mx1, fmaxf(sc[nt][2], sc[nt][3]));
        }
        mx0 = fmaxf(mx0, __shfl_xor_sync(0xffffffffu, mx0, 1));
        mx0 = fmaxf(mx0, __shfl_xor_sync(0xffffffffu, mx0, 2));
        mx1 = fmaxf(mx1, __shfl_xor_sync(0xffffffffu, mx1, 1));
        mx1 = fmaxf(mx1, __shfl_xor_sync(0xffffffffu, mx1, 2));
        float m0n = fmaxf(m0, mx0), m1n = fmaxf(m1, mx1);
        float a0 = __expf(m0 - m0n), a1 = __expf(m1 - m1n);
        m0 = m0n; m1 = m1n;

        float s0 = 0.f, s1 = 0.f;
        uint32_t pf[4][4];
        #pragma unroll
        for (int nt = 0; nt < 8; nt++) {
            float p0 = __expf(sc[nt][0] - m0);
            float p1 = __expf(sc[nt][1] - m0);
            float p2 = __expf(sc[nt][2] - m1);
            float p3 = __expf(sc[nt][3] - m1);
            s0 += p0 + p1; s1 += p2 + p3;
            __half2 h01 = __floats2half2_rn(p0, p1);
            __half2 h23 = __floats2half2_rn(p2, p3);
            pf[nt >> 1][(nt & 1) * 2 + 0] = *(uint32_t*)&h01;
            pf[nt >> 1][(nt & 1) * 2 + 1] = *(uint32_t*)&h23;
        }
        l0 = l0 * a0 + s0;
        l1 = l1 * a1 + s1;
        #pragma unroll
        for (int nt = 0; nt < 8; nt++) {
            oacc[nt][0] *= a0; oacc[nt][1] *= a0;
            oacc[nt][2] *= a1; oacc[nt][3] *= a1;
        }

        // ---- O += P @ V ----
        #pragma unroll
        for (int ks = 0; ks < 4; ks++) {
            uint32_t vf[4][4];
            #pragma unroll
            for (int j = 0; j < 4; j++) {
                int r = ks * 16 + ((lane >> 3) & 1) * 8 + (lane & 7);
                int c = j * 2 + (lane >> 4);
                ldsm4t(vf[j], vb + r * 128 + SWC(c, r));
            }
            #pragma unroll
            for (int j = 0; j < 4; j++) {
                mma16816(oacc[2 * j],     pf[ks], vf[j]);
                mma16816(oacc[2 * j + 1], pf[ks], vf[j] + 2);
            }
        }
        __syncthreads();
    }

    // ---- finalize: quad-reduce l, normalize, write fp16 ----
    l0 += __shfl_xor_sync(0xffffffffu, l0, 1);
    l0 += __shfl_xor_sync(0xffffffffu, l0, 2);
    l1 += __shfl_xor_sync(0xffffffffu, l1, 1);
    l1 += __shfl_xor_sync(0xffffffffu, l1, 2);
    float inv0 = 1.0f / l0, inv1 = 1.0f / l1;
    #pragma unroll
    for (int nt = 0; nt < 8; nt++) {
        int cc = h * 64 + nt * 8 + (lane & 3) * 2;
        *(__half2*)(o + (size_t)qrow0 * DMODEL + cc) =
            __floats2half2_rn(oacc[nt][0] * inv0, oacc[nt][1] * inv0);
        *(__half2*)(o + (size_t)(qrow0 + 8) * DMODEL + cc) =
            __floats2half2_rn(oacc[nt][2] * inv1, oacc[nt][3] * inv1);
    }
}

// ---------------- host orchestration ----------------
extern "C" void kernel_launch(void* const* d_in, const int* in_sizes, int n_in,
                              void* d_out, int out_size)
{
    const int*   idx    = (const int*)  d_in[0];
    const float* temb   = (const float*)d_in[1];
    const float* pe     = (const float*)d_in[2];
    const float* qkv_w  = (const float*)d_in[3];
    const float* qkv_b  = (const float*)d_in[4];
    const float* out_w  = (const float*)d_in[5];
    const float* out_b  = (const float*)d_in[6];
    const float* ln1_s  = (const float*)d_in[7];
    const float* ln1_b  = (const float*)d_in[8];
    const float* ln2_s  = (const float*)d_in[9];
    const float* ln2_b  = (const float*)d_in[10];
    const float* w1     = (const float*)d_in[11];
    const float* b1     = (const float*)d_in[12];
    const float* w2     = (const float*)d_in[13];
    const float* b2     = (const float*)d_in[14];
    float* out = (float*)d_out;

    float* x;
    __half *hbuf, *qkvb, *att, *ffn, *wt;
    cudaGetSymbolAddress((void**)&x,    g_x);
    cudaGetSymbolAddress((void**)&hbuf, g_h);
    cudaGetSymbolAddress((void**)&qkvb, g_qkv);
    cudaGetSymbolAddress((void**)&att,  g_att);
    cudaGetSymbolAddress((void**)&ffn,  g_ffn);
    cudaGetSymbolAddress((void**)&wt,   g_wt);

    constexpr int SMB128 = (64 + 128) * 128 * 2;   // 49152
    constexpr int SMB64  = (64 + 64) * 128 * 2;    // 32768
    constexpr int SMATT  = 8192 + 2 * 16384;       // 40960
    cudaFuncSetAttribute(hgemm_kernel<128, 0>, cudaFuncAttributeMaxDynamicSharedMemorySize, SMB128);
    cudaFuncSetAttribute(hgemm_kernel<128, 1>, cudaFuncAttributeMaxDynamicSharedMemorySize, SMB128);
    cudaFuncSetAttribute(hgemm_kernel<64, 2>,  cudaFuncAttributeMaxDynamicSharedMemorySize, SMB64);
    cudaFuncSetAttribute(fattn_kernel,         cudaFuncAttributeMaxDynamicSharedMemorySize, SMATT);

    wconv_all_kernel<<<2 * 6912, dim3(32, 8)>>>(qkv_w, out_w, w1, w2, wt);
    embed_kernel<<<S_LEN, 256>>>(idx, temb, pe, x);

    for (int l = 0; l < NLAYER; l++) {
        __half* wl = wt + (size_t)l * WT_LAYER;
        const float* lqkv_b = qkv_b + (size_t)l * 3 * DMODEL;
        const float* lout_b = out_b + (size_t)l * DMODEL;
        const float* lb1    = b1 + (size_t)l * FFN;
        const float* lb2    = b2 + (size_t)l * DMODEL;

        ln_kernel<<<S_LEN, 256>>>(x, ln1_s + l * DMODEL, ln1_b + l * DMODEL, hbuf);
        hgemm_kernel<128, 0><<<dim3(3 * DMODEL / 128, S_LEN / 64), 256, SMB128>>>(
            hbuf, wl + OQKV, lqkv_b, nullptr, qkvb, S_LEN, 3 * DMODEL, DMODEL);
        fattn_kernel<<<dim3(S_LEN / 64, NHEAD), 128, SMATT>>>(qkvb, att);
        hgemm_kernel<64, 2><<<dim3(DMODEL / 64, S_LEN / 64), 128, SMB64>>>(
            att, wl + OOUT, lout_b, x, x, S_LEN, DMODEL, DMODEL);
        ln_kernel<<<S_LEN, 256>>>(x, ln2_s + l * DMODEL, ln2_b + l * DMODEL, hbuf);
        hgemm_kernel<128, 1><<<dim3(FFN / 128, S_LEN / 64), 256, SMB128>>>(
            hbuf, wl + OW1, lb1, nullptr, ffn, S_LEN, FFN, DMODEL);
        float* dst = (l == NLAYER - 1) ? out : x;
        hgemm_kernel<64, 2><<<dim3(DMODEL / 64, S_LEN / 64), 128, SMB64>>>(
            ffn, wl + OW2, lb2, x, dst, S_LEN, DMODEL, FFN);
    }
}